// round 3
// baseline (speedup 1.0000x reference)
#include <cuda_runtime.h>

// Problem constants
#define TB 64           // batch
#define TT 1024         // time steps
#define TI 64           // input size
#define TH 256          // hidden size
#define NGROUP 4        // independent batch groups
#define CPG 32          // CTAs per group
#define BPG 16          // batches per group
#define UPC 16          // units per CTA per layer (512 units / 32 CTAs)
#define NCTA (NGROUP*CPG)
#define NTHR 256
#define K0 (TI + TH)    // 320 : layer0 concat [x ; h0_d]
#define K1 (2*TH + TH)  // 768 : layer1 concat [h0cat ; h1_d]
#define CHUNK 128
#define SXS 17          // padded smem X stride (16 batches + 1)

// ---------------- device scratch (static: no runtime allocation) ----------------
__device__ float g_xT[TT * TI * TB];      // transposed input: [t][i][b], 16 MB
__device__ float g_h0[2 * 512 * TB];      // [parity][unit(d*256+j)][batch]
__device__ float g_h1[2 * 512 * TB];
__device__ int      g_bar_count[NGROUP];  // zero-init at module load; invariant 0 between launches
__device__ unsigned g_bar_gen[NGROUP];    // monotonic generation counters

// ---------------- input transpose: x[b][t][i] -> g_xT[t][i][b] ----------------
__global__ void transpose_kernel(const float* __restrict__ x) {
    int idx = blockIdx.x * blockDim.x + threadIdx.x;
    if (idx < TT * TI * TB) {
        int b = idx & 63;
        int i = (idx >> 6) & 63;
        int t = idx >> 12;
        g_xT[idx] = x[(b * TT + t) * TI + i];
    }
}

__device__ __forceinline__ float sigmf(float v) {
    return 1.0f / (1.0f + __expf(-v));
}
__device__ __forceinline__ float tanh_fast(float v) {
    return 2.0f / (1.0f + __expf(-2.0f * v)) - 1.0f;
}

// ---------------- group barrier (sense via monotonic generation) ----------------
__device__ __forceinline__ void group_barrier(int grp, unsigned target) {
    __syncthreads();
    if (threadIdx.x == 0) {
        __threadfence();                       // release: h stores visible
        int prev = atomicAdd(&g_bar_count[grp], 1);
        if (prev == CPG - 1) {
            atomicExch(&g_bar_count[grp], 0);  // reset before releasing waiters
            __threadfence();
            atomicAdd(&g_bar_gen[grp], 1u);
        } else {
            while (atomicAdd(&g_bar_gen[grp], 0u) < target) { }
        }
        __threadfence();                       // acquire: subsequent h loads fresh
    }
    __syncthreads();
}

// load rows*16 X values into smem: sx[k][b] = src[k*64 + b] (src already offset by group batch base)
__device__ __forceinline__ void load_chunk(float* __restrict__ sx,
                                           const float* __restrict__ src, int rows) {
    for (int e = threadIdx.x; e < rows * BPG; e += NTHR) {
        int k = e >> 4;
        int b = e & 15;
        sx[k * SXS + b] = __ldcg(src + k * TB + b);
    }
}

// accumulate 3-gate dot products over LEN contiguous K positions
template <int LEN>
__device__ __forceinline__ void accum(const float* __restrict__ sw, const float* __restrict__ sx,
                                      int lu, int b, int wofs, int Kt,
                                      float& aR, float& aZ, float& aN) {
    const float* wr = sw + (lu * 3 + 0) * Kt + wofs;
    const float* wz = sw + (lu * 3 + 1) * Kt + wofs;
    const float* wn = sw + (lu * 3 + 2) * Kt + wofs;
    const float* xb = sx + b;
#pragma unroll 8
    for (int q = 0; q < LEN; q += 4) {
        float4 r4 = *reinterpret_cast<const float4*>(wr + q);
        float4 z4 = *reinterpret_cast<const float4*>(wz + q);
        float4 n4 = *reinterpret_cast<const float4*>(wn + q);
        float x0 = xb[(q + 0) * SXS];
        float x1 = xb[(q + 1) * SXS];
        float x2 = xb[(q + 2) * SXS];
        float x3 = xb[(q + 3) * SXS];
        aR = fmaf(r4.x, x0, aR); aZ = fmaf(z4.x, x0, aZ); aN = fmaf(n4.x, x0, aN);
        aR = fmaf(r4.y, x1, aR); aZ = fmaf(z4.y, x1, aZ); aN = fmaf(n4.y, x1, aN);
        aR = fmaf(r4.z, x2, aR); aZ = fmaf(z4.z, x2, aZ); aN = fmaf(n4.z, x2, aN);
        aR = fmaf(r4.w, x3, aR); aZ = fmaf(z4.w, x3, aZ); aN = fmaf(n4.w, x3, aN);
    }
}

// ---------------- persistent GRU kernel ----------------
__global__ void __launch_bounds__(NTHR, 1) gru_persistent(
    const float* __restrict__ W_ih0, const float* __restrict__ W_hh0,
    const float* __restrict__ b_ih0, const float* __restrict__ b_hh0,
    const float* __restrict__ W_ih1, const float* __restrict__ W_hh1,
    const float* __restrict__ b_ih1, const float* __restrict__ b_hh1,
    const int* __restrict__ seq_len, float* __restrict__ out)
{
    extern __shared__ float smem[];
    float* sw0 = smem;                     // [UPC][3][K0]
    float* sw1 = sw0 + UPC * 3 * K0;       // [UPC][3][K1]
    float* sx  = sw1 + UPC * 3 * K1;       // [CHUNK][SXS]

    const int tid = threadIdx.x;
    const int cta = blockIdx.x;
    const int grp = cta / CPG;
    const int cg  = cta % CPG;
    const int d     = cg >> 4;             // direction handled by this CTA (both layers)
    const int jbase = (cg & 15) * UPC;     // 16 hidden units
    const int gb    = grp * BPG;           // group batch base

    const int lu = tid >> 4;               // local unit  0..15
    const int b  = tid & 15;               // local batch 0..15
    const int j  = jbase + lu;
    const int u  = d * TH + j;             // global unit 0..511

    // ---- stage this CTA's weight rows into smem (concat [W_ih | W_hh] along K) ----
    for (int idx = tid; idx < UPC * 3 * K0; idx += NTHR) {
        int k  = idx % K0;
        int g  = (idx / K0) % 3;
        int lw = idx / (3 * K0);
        int row = d * (3 * TH) + g * TH + (jbase + lw);
        sw0[idx] = (k < TI) ? W_ih0[row * TI + k] : W_hh0[row * TH + (k - TI)];
    }
    for (int idx = tid; idx < UPC * 3 * K1; idx += NTHR) {
        int k  = idx % K1;
        int g  = (idx / K1) % 3;
        int lw = idx / (3 * K1);
        int row = d * (3 * TH) + g * TH + (jbase + lw);
        sw1[idx] = (k < 2 * TH) ? W_ih1[row * (2 * TH) + k] : W_hh1[row * TH + (k - 2 * TH)];
    }

    // biases (per thread's unit)
    const int brow = d * (3 * TH);
    const float bi0r = b_ih0[brow + j],          bh0r = b_hh0[brow + j];
    const float bi0z = b_ih0[brow + TH + j],     bh0z = b_hh0[brow + TH + j];
    const float bi0n = b_ih0[brow + 2 * TH + j], bh0n = b_hh0[brow + 2 * TH + j];
    const float bi1r = b_ih1[brow + j],          bh1r = b_hh1[brow + j];
    const float bi1z = b_ih1[brow + TH + j],     bh1z = b_hh1[brow + TH + j];
    const float bi1n = b_ih1[brow + 2 * TH + j], bh1n = b_hh1[brow + 2 * TH + j];

    int myidx = seq_len[gb + b] - 1;
    if (myidx < 0) myidx = 0;
    if (myidx > TT - 1) myidx = TT - 1;

    // ---- zero initial hidden state (parity 0), one (u,b) pair per thread ----
    __stcg(&g_h0[u * TB + gb + b], 0.0f);
    __stcg(&g_h1[u * TB + gb + b], 0.0f);

    __shared__ unsigned s_genbase;
    if (tid == 0) s_genbase = atomicAdd(&g_bar_gen[grp], 0u);
    __syncthreads();
    const unsigned genbase = s_genbase;
    unsigned nbar = 0;

    // prologue barrier: zeros visible group-wide before first step
    nbar++; group_barrier(grp, genbase + nbar);

    for (int t = 0; t < TT; ++t) {
        const int rp = t & 1, wp = rp ^ 1;
        const float* h0r = g_h0 + rp * (512 * TB);
        float*       h0w = g_h0 + wp * (512 * TB);
        const float* h1r = g_h1 + rp * (512 * TB);
        float*       h1w = g_h1 + wp * (512 * TB);

        // ================= layer 0 =================
        float aR = bi0r + bh0r, aZ = bi0z + bh0z, aNi = bi0n, aNh = bh0n;

        // input part (K = 64)
        load_chunk(sx, g_xT + t * (TI * TB) + gb, TI);
        __syncthreads();
        accum<TI>(sw0, sx, lu, b, 0, K0, aR, aZ, aNi);
        __syncthreads();
        // hidden part (K = 256)
#pragma unroll
        for (int c = 0; c < 2; ++c) {
            load_chunk(sx, h0r + (d * TH + c * CHUNK) * TB + gb, CHUNK);
            __syncthreads();
            accum<CHUNK>(sw0, sx, lu, b, TI + c * CHUNK, K0, aR, aZ, aNh);
            __syncthreads();
        }
        {
            float hp = __ldcg(h0r + u * TB + gb + b);
            float r  = sigmf(aR);
            float z  = sigmf(aZ);
            float n  = tanh_fast(aNi + r * aNh);
            float hn = n + z * (hp - n);
            __stcg(h0w + u * TB + gb + b, hn);
        }

        // single barrier per step: h0(t) published to the group
        nbar++; group_barrier(grp, genbase + nbar);

        // ================= layer 1 =================
        aR = bi1r + bh1r; aZ = bi1z + bh1z; aNi = bi1n; aNh = bh1n;

        // input part: full h0 concat (K = 512)
#pragma unroll
        for (int c = 0; c < 4; ++c) {
            load_chunk(sx, h0w + (c * CHUNK) * TB + gb, CHUNK);
            __syncthreads();
            accum<CHUNK>(sw1, sx, lu, b, c * CHUNK, K1, aR, aZ, aNi);
            __syncthreads();
        }
        // hidden part (K = 256)
#pragma unroll
        for (int c = 0; c < 2; ++c) {
            load_chunk(sx, h1r + (d * TH + c * CHUNK) * TB + gb, CHUNK);
            __syncthreads();
            accum<CHUNK>(sw1, sx, lu, b, 2 * TH + c * CHUNK, K1, aR, aZ, aNh);
            __syncthreads();
        }
        {
            float hp = __ldcg(h1r + u * TB + gb + b);
            float r  = sigmf(aR);
            float z  = sigmf(aZ);
            float n  = tanh_fast(aNi + r * aNh);
            float hn = n + z * (hp - n);
            __stcg(h1w + u * TB + gb + b, hn);
            if (t == myidx) out[(gb + b) * (2 * TH) + u] = hn;   // hidden[0][b][d*256+j]
        }
        // no trailing barrier needed: next step's phase1 touches no buffer
        // concurrently accessed by a lagging phase2 (proved by parity analysis)
    }
}

// ---------------- launch ----------------
extern "C" void kernel_launch(void* const* d_in, const int* in_sizes, int n_in,
                              void* d_out, int out_size) {
    const float* x     = (const float*)d_in[0];
    const float* W_ih0 = (const float*)d_in[1];
    const float* W_hh0 = (const float*)d_in[2];
    const float* b_ih0 = (const float*)d_in[3];
    const float* b_hh0 = (const float*)d_in[4];
    const float* W_ih1 = (const float*)d_in[5];
    const float* W_hh1 = (const float*)d_in[6];
    const float* b_ih1 = (const float*)d_in[7];
    const float* b_hh1 = (const float*)d_in[8];
    const int*   seqlv = (const int*)d_in[9];
    float* out = (float*)d_out;

    const size_t SMEM_BYTES = (size_t)(UPC * 3 * K0 + UPC * 3 * K1 + CHUNK * SXS) * sizeof(float);
    cudaFuncSetAttribute(gru_persistent, cudaFuncAttributeMaxDynamicSharedMemorySize,
                         (int)SMEM_BYTES);

    transpose_kernel<<<(TT * TI * TB + 255) / 256, 256>>>(x);
    gru_persistent<<<NCTA, NTHR, SMEM_BYTES>>>(W_ih0, W_hh0, b_ih0, b_hh0,
                                               W_ih1, W_hh1, b_ih1, b_hh1,
                                               seqlv, out);
}

// round 4
// speedup vs baseline: 1.0495x; 1.0495x over previous
#include <cuda_runtime.h>

// ---------------- problem constants ----------------
#define TB 64           // batch
#define TT 1024         // time steps
#define TI 64           // input size
#define TH 256          // hidden size
#define NGROUP 4        // independent batch groups
#define CPG 32          // CTAs per group
#define BPG 16          // batches per group
#define NCTA (NGROUP*CPG)
#define NTHR 256
#define K0 320          // layer0 concat [x(64) ; h0_d(256)]
#define K1 768          // layer1 concat [h0cat(512) ; h1_d(256)]
#define SXK 264         // smem x row stride (256 chunk + 8 pad), floats
#define BP  17          // gates buffer batch stride

// smem partition (floats)
#define OFS_SW0 0
#define OFS_SW1 (48*K0)                       // 15360
#define OFS_SX  (OFS_SW1 + 48*K1)             // 52224
#define OFS_GA  (OFS_SX + 16*SXK)             // 56448 : [48 rows][BP]
#define OFS_GB  (OFS_GA + 48*BP)              // 57264 : [16 units][BP] (n-gate hidden part)
#define SMEM_FLOATS (OFS_GB + 16*BP)          // 57536 -> 230144 bytes

// ---------------- device scratch ----------------
__device__ float g_xT[TT * TB * TI];          // [t][b][i]  (k-major per batch)
__device__ float g_h0[2 * TB * 512];          // [parity][b][u],  u = d*256 + j
__device__ float g_h1[2 * TB * 512];
__device__ int      g_bar_count[NGROUP];
__device__ unsigned g_bar_gen[NGROUP];

// ---------------- input transpose: x[b][t][i] -> g_xT[t][b][i] ----------------
__global__ void transpose_kernel(const float* __restrict__ x) {
    int idx = blockIdx.x * blockDim.x + threadIdx.x;
    if (idx < TT * TB * TI) {
        int i = idx & 63;
        int b = (idx >> 6) & 63;
        int t = idx >> 12;
        g_xT[idx] = x[(b * TT + t) * TI + i];
    }
}

__device__ __forceinline__ float sigmf(float v) { return 1.0f / (1.0f + __expf(-v)); }
__device__ __forceinline__ float tanh_fast(float v) { return 2.0f / (1.0f + __expf(-2.0f * v)) - 1.0f; }

// packed fp32x2 FMA (Blackwell): acc = a*b + acc, elementwise on 2 floats
__device__ __forceinline__ void fma2(unsigned long long& acc,
                                     unsigned long long a, unsigned long long b) {
    asm("fma.rn.f32x2 %0, %1, %2, %0;" : "+l"(acc) : "l"(a), "l"(b));
}

// ---------------- group barrier ----------------
__device__ __forceinline__ void group_barrier(int grp, unsigned target) {
    __syncthreads();
    if (threadIdx.x == 0) {
        __threadfence();
        int prev = atomicAdd(&g_bar_count[grp], 1);
        if (prev == CPG - 1) {
            atomicExch(&g_bar_count[grp], 0);
            __threadfence();
            atomicAdd(&g_bar_gen[grp], 1u);
        } else {
            while (atomicAdd(&g_bar_gen[grp], 0u) < target) { }
        }
        __threadfence();
    }
    __syncthreads();
}

// stage CH floats per batch-row (16 rows) into sx[b][k], k-contiguous both sides
template <int CH>
__device__ __forceinline__ void stage(float* __restrict__ sx,
                                      const float* __restrict__ src, int srcStride) {
    constexpr int NV = CH / 4;
    for (int idx = threadIdx.x; idx < 16 * NV; idx += NTHR) {
        int bl = idx / NV;
        int kk = idx - bl * NV;
        float4 v = __ldcg(reinterpret_cast<const float4*>(src + bl * srcStride) + kk);
        *reinterpret_cast<float4*>(sx + bl * SXK + kk * 4) = v;
    }
}

// split-K register-tiled accumulation: warp owns 6 rows x 16 batches,
// lane (ks = lane>>2, c = lane&3) owns 6 rows x 4 batches over k-slice ks.
// acc[r][i] holds packed (even k, odd k) partial sums.
template <int ITERS>
__device__ __forceinline__ void accum_chunk(unsigned long long acc[6][4],
                                            const float* __restrict__ wbase, int K,
                                            const float* __restrict__ sx,
                                            int ks, int c) {
    const float* xb = sx + (c * 4) * SXK;
#pragma unroll
    for (int j = 0; j < ITERS; ++j) {
        int k4 = (j * 8 + ks) * 4;
        ulonglong2 xv[4], wv[6];
#pragma unroll
        for (int i = 0; i < 4; ++i)
            xv[i] = *reinterpret_cast<const ulonglong2*>(xb + i * SXK + k4);
#pragma unroll
        for (int r = 0; r < 6; ++r)
            wv[r] = *reinterpret_cast<const ulonglong2*>(wbase + r * K + k4);
#pragma unroll
        for (int r = 0; r < 6; ++r)
#pragma unroll
            for (int i = 0; i < 4; ++i) {
                fma2(acc[r][i], wv[r].x, xv[i].x);
                fma2(acc[r][i], wv[r].y, xv[i].y);
            }
    }
}

__device__ __forceinline__ void fold(unsigned long long acc[6][4], float out[6][4]) {
#pragma unroll
    for (int r = 0; r < 6; ++r)
#pragma unroll
        for (int i = 0; i < 4; ++i) {
            union { unsigned long long u; float2 f; } cv;
            cv.u = acc[r][i];
            out[r][i] = cv.f.x + cv.f.y;
            acc[r][i] = 0ull;
        }
}

// cross-slice reduction + publish gate sums to smem
__device__ __forceinline__ void reduce_store(const float aI[6][4], const float aH[6][4],
                                             int rw, int lane,
                                             float* __restrict__ GA, float* __restrict__ GB) {
    int c = lane & 3;
#pragma unroll
    for (int r = 0; r < 6; ++r) {
        int row = rw + r;
        if (row < 32) {            // r/z gates: only the total is needed
#pragma unroll
            for (int i = 0; i < 4; ++i) {
                float s = aI[r][i] + aH[r][i];
                s += __shfl_xor_sync(0xffffffffu, s, 4);
                s += __shfl_xor_sync(0xffffffffu, s, 8);
                s += __shfl_xor_sync(0xffffffffu, s, 16);
                if (lane < 4) GA[row * BP + c * 4 + i] = s;
            }
        } else {                   // n gate: keep input / hidden parts separate
#pragma unroll
            for (int i = 0; i < 4; ++i) {
                float s = aI[r][i];
                s += __shfl_xor_sync(0xffffffffu, s, 4);
                s += __shfl_xor_sync(0xffffffffu, s, 8);
                s += __shfl_xor_sync(0xffffffffu, s, 16);
                float h = aH[r][i];
                h += __shfl_xor_sync(0xffffffffu, h, 4);
                h += __shfl_xor_sync(0xffffffffu, h, 8);
                h += __shfl_xor_sync(0xffffffffu, h, 16);
                if (lane < 4) {
                    GA[row * BP + c * 4 + i] = s;
                    GB[(row - 32) * BP + c * 4 + i] = h;
                }
            }
        }
    }
}

// ---------------- persistent GRU kernel ----------------
__global__ void __launch_bounds__(NTHR, 1) gru_persistent(
    const float* __restrict__ W_ih0, const float* __restrict__ W_hh0,
    const float* __restrict__ b_ih0, const float* __restrict__ b_hh0,
    const float* __restrict__ W_ih1, const float* __restrict__ W_hh1,
    const float* __restrict__ b_ih1, const float* __restrict__ b_hh1,
    const int* __restrict__ seq_len, float* __restrict__ out)
{
    extern __shared__ float smem[];
    float* sw0 = smem + OFS_SW0;   // [48 rows][K0], row = g*16+lw, k-contiguous
    float* sw1 = smem + OFS_SW1;   // [48 rows][K1]
    float* sx  = smem + OFS_SX;    // [16 b][SXK]
    float* GA  = smem + OFS_GA;    // [48][BP]
    float* GB  = smem + OFS_GB;    // [16][BP]

    const int tid = threadIdx.x;
    const int cta = blockIdx.x;
    const int grp = cta / CPG;
    const int cg  = cta % CPG;
    const int d     = cg >> 4;
    const int jbase = (cg & 15) * 16;
    const int gb    = grp * BPG;

    // compute mapping (warp/lane)
    const int warp = tid >> 5;
    const int lane = tid & 31;
    const int ks   = lane >> 2;
    const int c    = lane & 3;
    const int rw   = warp * 6;

    // output mapping (unit/batch)
    const int lu = tid & 15;
    const int b  = tid >> 4;
    const int j  = jbase + lu;
    const int u  = d * TH + j;

    // ---- stage weights into smem ----
    for (int idx = tid; idx < 48 * K0; idx += NTHR) {
        int k = idx % K0, r = idx / K0;
        int grow = d * 768 + (r >> 4) * 256 + jbase + (r & 15);
        sw0[idx] = (k < TI) ? W_ih0[grow * TI + k] : W_hh0[grow * TH + (k - TI)];
    }
    for (int idx = tid; idx < 48 * K1; idx += NTHR) {
        int k = idx % K1, r = idx / K1;
        int grow = d * 768 + (r >> 4) * 256 + jbase + (r & 15);
        sw1[idx] = (k < 512) ? W_ih1[grow * 512 + k] : W_hh1[grow * TH + (k - 512)];
    }

    // biases for this thread's unit
    const int base = d * 768;
    const float b0r = b_ih0[base + j] + b_hh0[base + j];
    const float b0z = b_ih0[base + TH + j] + b_hh0[base + TH + j];
    const float b0ni = b_ih0[base + 2 * TH + j];
    const float b0nh = b_hh0[base + 2 * TH + j];
    const float b1r = b_ih1[base + j] + b_hh1[base + j];
    const float b1z = b_ih1[base + TH + j] + b_hh1[base + TH + j];
    const float b1ni = b_ih1[base + 2 * TH + j];
    const float b1nh = b_hh1[base + 2 * TH + j];

    int myidx = seq_len[gb + b] - 1;
    if (myidx < 0) myidx = 0;
    if (myidx > TT - 1) myidx = TT - 1;

    // zero initial hidden state, parity 0 : h[0][b][u]
    __stcg(&g_h0[(gb + b) * 512 + u], 0.0f);
    __stcg(&g_h1[(gb + b) * 512 + u], 0.0f);

    __shared__ unsigned s_genbase;
    if (tid == 0) s_genbase = atomicAdd(&g_bar_gen[grp], 0u);
    __syncthreads();
    const unsigned genbase = s_genbase;
    unsigned nbar = 0;

    nbar++; group_barrier(grp, genbase + nbar);   // zeros + weights visible

    unsigned long long acc[6][4];
#pragma unroll
    for (int r = 0; r < 6; ++r)
#pragma unroll
        for (int i = 0; i < 4; ++i) acc[r][i] = 0ull;

    for (int t = 0; t < TT; ++t) {
        const int rp = t & 1, wp = rp ^ 1;
        const float* h0r = g_h0 + rp * (TB * 512);
        float*       h0w = g_h0 + wp * (TB * 512);
        const float* h1r = g_h1 + rp * (TB * 512);
        float*       h1w = g_h1 + wp * (TB * 512);

        float aI[6][4], aH[6][4];

        // ================= layer 0 =================
        // input part: x[t], K=64
        __syncthreads();
        stage<64>(sx, g_xT + t * (TB * TI) + gb * TI, TI);
        __syncthreads();
        accum_chunk<2>(acc, sw0 + rw * K0, K0, sx, ks, c);
        fold(acc, aI);
        // hidden part: h0_d, K=256
        __syncthreads();
        stage<256>(sx, h0r + gb * 512 + d * TH, 512);
        __syncthreads();
        accum_chunk<8>(acc, sw0 + rw * K0 + TI, K0, sx, ks, c);
        fold(acc, aH);
        reduce_store(aI, aH, rw, lane, GA, GB);
        __syncthreads();
        {
            float aR  = GA[lu * BP + b] + b0r;
            float aZ  = GA[(16 + lu) * BP + b] + b0z;
            float aNi = GA[(32 + lu) * BP + b] + b0ni;
            float aNh = GB[lu * BP + b] + b0nh;
            float hp = __ldcg(h0r + (gb + b) * 512 + u);
            float r  = sigmf(aR);
            float z  = sigmf(aZ);
            float n  = tanh_fast(aNi + r * (aNh));
            float hn = n + z * (hp - n);
            __stcg(h0w + (gb + b) * 512 + u, hn);
        }

        // single cross-CTA barrier per step: h0(t) published group-wide
        nbar++; group_barrier(grp, genbase + nbar);

        // ================= layer 1 =================
        // input part: h0 concat (512) in 2 chunks
#pragma unroll
        for (int ch = 0; ch < 2; ++ch) {
            __syncthreads();
            stage<256>(sx, h0w + gb * 512 + ch * 256, 512);
            __syncthreads();
            accum_chunk<8>(acc, sw1 + rw * K1 + ch * 256, K1, sx, ks, c);
        }
        fold(acc, aI);
        // hidden part: h1_d (256)
        __syncthreads();
        stage<256>(sx, h1r + gb * 512 + d * TH, 512);
        __syncthreads();
        accum_chunk<8>(acc, sw1 + rw * K1 + 512, K1, sx, ks, c);
        fold(acc, aH);
        reduce_store(aI, aH, rw, lane, GA, GB);
        __syncthreads();
        {
            float aR  = GA[lu * BP + b] + b1r;
            float aZ  = GA[(16 + lu) * BP + b] + b1z;
            float aNi = GA[(32 + lu) * BP + b] + b1ni;
            float aNh = GB[lu * BP + b] + b1nh;
            float hp = __ldcg(h1r + (gb + b) * 512 + u);
            float r  = sigmf(aR);
            float z  = sigmf(aZ);
            float n  = tanh_fast(aNi + r * (aNh));
            float hn = n + z * (hp - n);
            __stcg(h1w + (gb + b) * 512 + u, hn);
            if (t == myidx) out[(gb + b) * (2 * TH) + u] = hn;
        }
        // no trailing barrier needed (parity analysis: fast CTA's next-step
        // writes can't touch buffers a lagging CTA still reads before it has
        // itself passed the next phase1->phase2 barrier)
    }
}

// ---------------- launch ----------------
extern "C" void kernel_launch(void* const* d_in, const int* in_sizes, int n_in,
                              void* d_out, int out_size) {
    const float* x     = (const float*)d_in[0];
    const float* W_ih0 = (const float*)d_in[1];
    const float* W_hh0 = (const float*)d_in[2];
    const float* b_ih0 = (const float*)d_in[3];
    const float* b_hh0 = (const float*)d_in[4];
    const float* W_ih1 = (const float*)d_in[5];
    const float* W_hh1 = (const float*)d_in[6];
    const float* b_ih1 = (const float*)d_in[7];
    const float* b_hh1 = (const float*)d_in[8];
    const int*   seqlv = (const int*)d_in[9];
    float* out = (float*)d_out;

    const size_t SMEM_BYTES = (size_t)SMEM_FLOATS * sizeof(float);
    cudaFuncSetAttribute(gru_persistent, cudaFuncAttributeMaxDynamicSharedMemorySize,
                         (int)SMEM_BYTES);

    transpose_kernel<<<(TT * TB * TI + 255) / 256, 256>>>(x);
    gru_persistent<<<NCTA, NTHR, SMEM_BYTES>>>(W_ih0, W_hh0, b_ih0, b_hh0,
                                               W_ih1, W_hh1, b_ih1, b_hh1,
                                               seqlv, out);
}

// round 7
// speedup vs baseline: 1.6920x; 1.6122x over previous
#include <cuda_runtime.h>

// ---------------- problem constants ----------------
#define TB 64           // batch
#define TT 1024         // time steps
#define TI 64           // input size
#define TH 256          // hidden size
#define NGROUP 4        // independent batch groups
#define CPG 32          // CTAs per group
#define BPG 16          // batches per group
#define NCTA (NGROUP*CPG)
#define NTHR 256
#define K0 320          // layer0 concat [x(64) ; h0_d(256)]
#define K1 768          // layer1 concat [h0cat(512) ; h1_d(256)]
#define SXK 132         // smem x row stride in floats (128 chunk + 4 pad, 16B aligned)
#define BP  17          // gates buffer batch stride

// smem partition (floats)
#define OFS_SW0 0
#define OFS_SW1 (48*K0)                       // 15360
#define OFS_SX  (OFS_SW1 + 48*K1)             // 52224 : 2 buffers [16][SXK]
#define OFS_GA  (OFS_SX + 2*16*SXK)           // 56448 : [48 rows][BP]
#define OFS_GB  (OFS_GA + 48*BP)              // 57264 : [16 units][BP]
#define SMEM_FLOATS (OFS_GB + 16*BP)          // 57536 floats = 230144 bytes

// ---------------- device scratch ----------------
__device__ float g_xT[TT * TB * TI];          // [t][b][i]
__device__ float g_h0[2 * TB * 512];          // [parity][b][u]
__device__ float g_h1[2 * TB * 512];
__device__ int      g_bar_count[NGROUP];
__device__ unsigned g_bar_gen[NGROUP];

// ---------------- input transpose ----------------
__global__ void transpose_kernel(const float* __restrict__ x) {
    int idx = blockIdx.x * blockDim.x + threadIdx.x;
    if (idx < TT * TB * TI) {
        int i = idx & 63;
        int b = (idx >> 6) & 63;
        int t = idx >> 12;
        g_xT[idx] = x[(b * TT + t) * TI + i];
    }
}

__device__ __forceinline__ float sigmf(float v) { return 1.0f / (1.0f + __expf(-v)); }
__device__ __forceinline__ float tanh_fast(float v) { return 2.0f / (1.0f + __expf(-2.0f * v)) - 1.0f; }

__device__ __forceinline__ void fma2(unsigned long long& acc,
                                     unsigned long long a, unsigned long long b) {
    asm("fma.rn.f32x2 %0, %1, %2, %0;" : "+l"(acc) : "l"(a), "l"(b));
}

// ---------------- cp.async helpers ----------------
__device__ __forceinline__ void cp16(float* s, const float* g) {
    unsigned ss = (unsigned)__cvta_generic_to_shared(s);
    asm volatile("cp.async.cg.shared.global [%0], [%1], 16;" :: "r"(ss), "l"(g) : "memory");
}
__device__ __forceinline__ void cp_commit() {
    asm volatile("cp.async.commit_group;" ::: "memory");
}
template <int N>
__device__ __forceinline__ void cp_wait() {
    asm volatile("cp.async.wait_group %0;" :: "n"(N) : "memory");
}

// stage CH floats per batch-row (16 rows) via cp.async
template <int CH>
__device__ __forceinline__ void stage_async(float* __restrict__ sx,
                                            const float* __restrict__ src, int srcStride) {
    constexpr int NV = CH / 4;
    for (int idx = threadIdx.x; idx < 16 * NV; idx += NTHR) {
        int bl = idx / NV;
        int kk = idx - bl * NV;
        cp16(sx + bl * SXK + kk * 4, src + bl * srcStride + kk * 4);
    }
    cp_commit();
}

// ---------------- group barrier ----------------
__device__ __forceinline__ void group_barrier(int grp, unsigned target) {
    __syncthreads();
    if (threadIdx.x == 0) {
        __threadfence();
        int prev = atomicAdd(&g_bar_count[grp], 1);
        if (prev == CPG - 1) {
            atomicExch(&g_bar_count[grp], 0);
            __threadfence();
            atomicAdd(&g_bar_gen[grp], 1u);
        } else {
            while (atomicAdd(&g_bar_gen[grp], 0u) < target) { }
        }
        __threadfence();
    }
    __syncthreads();
}

// split-K register-tiled accumulation.
// lane mapping: ks = lane & 7 (k-slice), c = lane >> 3 (batch quad).
// One j-iter: warp covers 32 consecutive k (8 slices x 4 floats).
// ITERS = chunk_len / 32.  Conflict-free: each quarter-warp phase has constant
// c and 8 consecutive ks -> 32 consecutive words spanning all banks; wv is a
// pure broadcast across quarter-warps.
template <int ITERS>
__device__ __forceinline__ void accum_chunk(unsigned long long acc[6][4],
                                            const float* __restrict__ wbase, int K,
                                            const float* __restrict__ sx,
                                            int ks, int c) {
    const float* xb = sx + (c * 4) * SXK;
#pragma unroll
    for (int j = 0; j < ITERS; ++j) {
        int k4 = (j * 8 + ks) * 4;
        ulonglong2 xv[4], wv[6];
#pragma unroll
        for (int i = 0; i < 4; ++i)
            xv[i] = *reinterpret_cast<const ulonglong2*>(xb + i * SXK + k4);
#pragma unroll
        for (int r = 0; r < 6; ++r)
            wv[r] = *reinterpret_cast<const ulonglong2*>(wbase + r * K + k4);
#pragma unroll
        for (int r = 0; r < 6; ++r)
#pragma unroll
            for (int i = 0; i < 4; ++i) {
                fma2(acc[r][i], wv[r].x, xv[i].x);
                fma2(acc[r][i], wv[r].y, xv[i].y);
            }
    }
}

__device__ __forceinline__ void fold(unsigned long long acc[6][4], float out[6][4]) {
#pragma unroll
    for (int r = 0; r < 6; ++r)
#pragma unroll
        for (int i = 0; i < 4; ++i) {
            union { unsigned long long u; float2 f; } cv;
            cv.u = acc[r][i];
            out[r][i] = cv.f.x + cv.f.y;
            acc[r][i] = 0ull;
        }
}

// cross-slice reduction (over ks = lane&7) + publish gate sums to smem
__device__ __forceinline__ void reduce_store(const float aI[6][4], const float aH[6][4],
                                             int rw, int lane,
                                             float* __restrict__ GA, float* __restrict__ GB) {
    int c = lane >> 3;
    bool wr = (lane & 7) == 0;
#pragma unroll
    for (int r = 0; r < 6; ++r) {
        int row = rw + r;
        if (row < 32) {            // r/z gates: only the total
#pragma unroll
            for (int i = 0; i < 4; ++i) {
                float s = aI[r][i] + aH[r][i];
                s += __shfl_xor_sync(0xffffffffu, s, 1);
                s += __shfl_xor_sync(0xffffffffu, s, 2);
                s += __shfl_xor_sync(0xffffffffu, s, 4);
                if (wr) GA[row * BP + c * 4 + i] = s;
            }
        } else {                   // n gate: input / hidden parts separate
#pragma unroll
            for (int i = 0; i < 4; ++i) {
                float s = aI[r][i];
                s += __shfl_xor_sync(0xffffffffu, s, 1);
                s += __shfl_xor_sync(0xffffffffu, s, 2);
                s += __shfl_xor_sync(0xffffffffu, s, 4);
                float h = aH[r][i];
                h += __shfl_xor_sync(0xffffffffu, h, 1);
                h += __shfl_xor_sync(0xffffffffu, h, 2);
                h += __shfl_xor_sync(0xffffffffu, h, 4);
                if (wr) {
                    GA[row * BP + c * 4 + i] = s;
                    GB[(row - 32) * BP + c * 4 + i] = h;
                }
            }
        }
    }
}

// ---------------- persistent GRU kernel ----------------
__global__ void __launch_bounds__(NTHR, 1) gru_persistent(
    const float* __restrict__ W_ih0, const float* __restrict__ W_hh0,
    const float* __restrict__ b_ih0, const float* __restrict__ b_hh0,
    const float* __restrict__ W_ih1, const float* __restrict__ W_hh1,
    const float* __restrict__ b_ih1, const float* __restrict__ b_hh1,
    const int* __restrict__ seq_len, float* __restrict__ out)
{
    extern __shared__ float smem[];
    float* sw0 = smem + OFS_SW0;   // [48 rows][K0]
    float* sw1 = smem + OFS_SW1;   // [48 rows][K1]
    float* sx0 = smem + OFS_SX;            // staging buffer 0
    float* sx1 = smem + OFS_SX + 16 * SXK; // staging buffer 1
    float* GA  = smem + OFS_GA;    // [48][BP]
    float* GB  = smem + OFS_GB;    // [16][BP]

    const int tid = threadIdx.x;
    const int cta = blockIdx.x;
    const int grp = cta / CPG;
    const int cg  = cta % CPG;
    const int d     = cg >> 4;
    const int jbase = (cg & 15) * 16;
    const int gb    = grp * BPG;

    const int warp = tid >> 5;
    const int lane = tid & 31;
    const int ks   = lane & 7;
    const int c    = lane >> 3;
    const int rw   = warp * 6;

    const int lu = tid & 15;
    const int b  = tid >> 4;
    const int j  = jbase + lu;
    const int u  = d * TH + j;

    // ---- stage weights into smem ----
    for (int idx = tid; idx < 48 * K0; idx += NTHR) {
        int k = idx % K0, r = idx / K0;
        int grow = d * 768 + (r >> 4) * 256 + jbase + (r & 15);
        sw0[idx] = (k < TI) ? W_ih0[grow * TI + k] : W_hh0[grow * TH + (k - TI)];
    }
    for (int idx = tid; idx < 48 * K1; idx += NTHR) {
        int k = idx % K1, r = idx / K1;
        int grow = d * 768 + (r >> 4) * 256 + jbase + (r & 15);
        sw1[idx] = (k < 512) ? W_ih1[grow * 512 + k] : W_hh1[grow * TH + (k - 512)];
    }

    const int base = d * 768;
    const float b0r = b_ih0[base + j] + b_hh0[base + j];
    const float b0z = b_ih0[base + TH + j] + b_hh0[base + TH + j];
    const float b0ni = b_ih0[base + 2 * TH + j];
    const float b0nh = b_hh0[base + 2 * TH + j];
    const float b1r = b_ih1[base + j] + b_hh1[base + j];
    const float b1z = b_ih1[base + TH + j] + b_hh1[base + TH + j];
    const float b1ni = b_ih1[base + 2 * TH + j];
    const float b1nh = b_hh1[base + 2 * TH + j];

    int myidx = seq_len[gb + b] - 1;
    if (myidx < 0) myidx = 0;
    if (myidx > TT - 1) myidx = TT - 1;

    __stcg(&g_h0[(gb + b) * 512 + u], 0.0f);
    __stcg(&g_h1[(gb + b) * 512 + u], 0.0f);

    __shared__ unsigned s_genbase;
    if (tid == 0) s_genbase = atomicAdd(&g_bar_gen[grp], 0u);
    __syncthreads();
    const unsigned genbase = s_genbase;
    unsigned nbar = 0;

    nbar++; group_barrier(grp, genbase + nbar);   // zeros + weights visible

    unsigned long long acc[6][4];
#pragma unroll
    for (int r = 0; r < 6; ++r)
#pragma unroll
        for (int i = 0; i < 4; ++i) acc[r][i] = 0ull;

    const float* sw0w = sw0 + rw * K0;
    const float* sw1w = sw1 + rw * K1;

    for (int t = 0; t < TT; ++t) {
        const int rp = t & 1, wp = rp ^ 1;
        const float* h0r = g_h0 + rp * (TB * 512);
        float*       h0w = g_h0 + wp * (TB * 512);
        const float* h1r = g_h1 + rp * (TB * 512);
        float*       h1w = g_h1 + wp * (TB * 512);

        float aI[6][4], aH[6][4];

        // ================= layer 0  (K = 64 + 256) =================
        stage_async<64>(sx0, g_xT + t * (TB * TI) + gb * TI, TI);          // A0 -> sx0
        stage_async<128>(sx1, h0r + gb * 512 + d * TH, 512);               // A1 -> sx1
        cp_wait<1>(); __syncthreads();                                     // A0 ready
        accum_chunk<2>(acc, sw0w, K0, sx0, ks, c);                         // 64 k
        fold(acc, aI);
        __syncthreads();                                                   // sx0 free
        stage_async<128>(sx0, h0r + gb * 512 + d * TH + 128, 512);         // A2 -> sx0
        cp_wait<1>(); __syncthreads();                                     // A1 ready
        accum_chunk<4>(acc, sw0w + TI, K0, sx1, ks, c);                    // 128 k
        cp_wait<0>(); __syncthreads();                                     // A2 ready
        accum_chunk<4>(acc, sw0w + TI + 128, K0, sx0, ks, c);              // 128 k
        fold(acc, aH);
        reduce_store(aI, aH, rw, lane, GA, GB);
        __syncthreads();
        {
            float aR  = GA[lu * BP + b] + b0r;
            float aZ  = GA[(16 + lu) * BP + b] + b0z;
            float aNi = GA[(32 + lu) * BP + b] + b0ni;
            float aNh = GB[lu * BP + b] + b0nh;
            float hp = __ldcg(h0r + (gb + b) * 512 + u);
            float r  = sigmf(aR);
            float z  = sigmf(aZ);
            float n  = tanh_fast(aNi + r * aNh);
            float hn = n + z * (hp - n);
            __stcg(h0w + (gb + b) * 512 + u, hn);
        }

        // single cross-CTA barrier per step: h0(t) published group-wide
        nbar++; group_barrier(grp, genbase + nbar);

        // ================= layer 1  (K = 512 + 256) =================
        stage_async<128>(sx0, h0w + gb * 512 + 0, 512);                    // B0
        stage_async<128>(sx1, h0w + gb * 512 + 128, 512);                  // B1
        cp_wait<1>(); __syncthreads();                                     // B0 ready
        accum_chunk<4>(acc, sw1w, K1, sx0, ks, c);
        __syncthreads();
        stage_async<128>(sx0, h0w + gb * 512 + 256, 512);                  // B2
        cp_wait<1>(); __syncthreads();                                     // B1 ready
        accum_chunk<4>(acc, sw1w + 128, K1, sx1, ks, c);
        __syncthreads();
        stage_async<128>(sx1, h0w + gb * 512 + 384, 512);                  // B3
        cp_wait<1>(); __syncthreads();                                     // B2 ready
        accum_chunk<4>(acc, sw1w + 256, K1, sx0, ks, c);
        __syncthreads();
        stage_async<128>(sx0, h1r + gb * 512 + d * TH, 512);               // B4
        cp_wait<1>(); __syncthreads();                                     // B3 ready
        accum_chunk<4>(acc, sw1w + 384, K1, sx1, ks, c);
        fold(acc, aI);
        __syncthreads();
        stage_async<128>(sx1, h1r + gb * 512 + d * TH + 128, 512);         // B5
        cp_wait<1>(); __syncthreads();                                     // B4 ready
        accum_chunk<4>(acc, sw1w + 512, K1, sx0, ks, c);
        cp_wait<0>(); __syncthreads();                                     // B5 ready
        accum_chunk<4>(acc, sw1w + 640, K1, sx1, ks, c);
        fold(acc, aH);
        reduce_store(aI, aH, rw, lane, GA, GB);
        __syncthreads();
        {
            float aR  = GA[lu * BP + b] + b1r;
            float aZ  = GA[(16 + lu) * BP + b] + b1z;
            float aNi = GA[(32 + lu) * BP + b] + b1ni;
            float aNh = GB[lu * BP + b] + b1nh;
            float hp = __ldcg(h1r + (gb + b) * 512 + u);
            float r  = sigmf(aR);
            float z  = sigmf(aZ);
            float n  = tanh_fast(aNi + r * aNh);
            float hn = n + z * (hp - n);
            __stcg(h1w + (gb + b) * 512 + u, hn);
            if (t == myidx) out[(gb + b) * (2 * TH) + u] = hn;
        }
        // next step's phase A stages issue only after the reduce_store sync,
        // so both sx buffers are safely reusable; cross-CTA ordering is by the
        // per-step group barrier (parity analysis unchanged from R3).
    }
}

// ---------------- launch ----------------
extern "C" void kernel_launch(void* const* d_in, const int* in_sizes, int n_in,
                              void* d_out, int out_size) {
    const float* x     = (const float*)d_in[0];
    const float* W_ih0 = (const float*)d_in[1];
    const float* W_hh0 = (const float*)d_in[2];
    const float* b_ih0 = (const float*)d_in[3];
    const float* b_hh0 = (const float*)d_in[4];
    const float* W_ih1 = (const float*)d_in[5];
    const float* W_hh1 = (const float*)d_in[6];
    const float* b_ih1 = (const float*)d_in[7];
    const float* b_hh1 = (const float*)d_in[8];
    const int*   seqlv = (const int*)d_in[9];
    float* out = (float*)d_out;

    const size_t SMEM_BYTES = (size_t)SMEM_FLOATS * sizeof(float);
    cudaFuncSetAttribute(gru_persistent, cudaFuncAttributeMaxDynamicSharedMemorySize,
                         (int)SMEM_BYTES);

    transpose_kernel<<<(TT * TB * TI + 255) / 256, 256>>>(x);
    gru_persistent<<<NCTA, NTHR, SMEM_BYTES>>>(W_ih0, W_hh0, b_ih0, b_hh0,
                                               W_ih1, W_hh1, b_ih1, b_hh1,
                                               seqlv, out);
}